// round 1
// baseline (speedup 1.0000x reference)
#include <cuda_runtime.h>

#define HID   64
#define CDIM  256     // HEADS*HID
#define NMAX  65536
#define EMAX  524288

// ---------------- scratch (static device arrays; no allocation) ----------------
__device__ float g_wc[3 * HID];          // combined embedding weight [3][64]
__device__ float g_bc[HID];              // combined embedding bias
__device__ float g_x [NMAX * HID];       // node embeddings
__device__ float g_xl[NMAX * CDIM];      // x @ gat_wl
__device__ float g_xr[NMAX * CDIM];      // x @ gat_wr
__device__ float g_y [NMAX * HID];       // post-LN features
__device__ int   g_deg [NMAX];
__device__ int   g_off [NMAX + 1];
__device__ int   g_cur [NMAX];
__device__ int   g_bsum[256];
__device__ int   g_total;
__device__ int   g_csr [EMAX];           // src per dst-sorted edge

// ---------------- helpers ----------------
__device__ __forceinline__ float decode_t(const void* p) {
    // timestep may arrive as int32/int64 (small value) or float32
    int iv = *(const int*)p;
    if (iv > -16777216 && iv < 16777216) return (float)iv;   // int32 / int64 low word
    return __int_as_float(iv);                               // float32
}

// ---------------- K0: combine embedding weights ----------------
__global__ void prep_kernel(const float* __restrict__ w1, const float* __restrict__ b1,
                            const float* __restrict__ w2, const float* __restrict__ b2) {
    int j = threadIdx.x;  // 64 threads
    float c0 = 0.f, c1 = 0.f, c2 = 0.f, cb = 0.f;
    for (int k = 0; k < HID; k++) {
        float wkj = w2[k * HID + j];
        c0 += w1[0 * HID + k] * wkj;
        c1 += w1[1 * HID + k] * wkj;
        c2 += w1[2 * HID + k] * wkj;
        cb += b1[k] * wkj;
    }
    g_wc[j]           = c0;
    g_wc[HID + j]     = c1;
    g_wc[2 * HID + j] = c2;
    g_bc[j]           = cb + b2[j];
}

// ---------------- K1: node features -> x ----------------
__global__ void feat_kernel(const float* __restrict__ arr, const float* __restrict__ dep,
                            const float* __restrict__ hard, const void* __restrict__ tptr,
                            int n) {
    int idx = blockIdx.x * blockDim.x + threadIdx.x;
    if (idx >= n * HID) return;
    int node = idx >> 6;
    int j    = idx & 63;
    float t = decode_t(tptr);
    float a = arr[node], d = dep[node];
    float prog = (t - a) / fmaxf(d - a, 1.0f);
    float atl  = ((d - t) <= 1.0f) ? 1.0f : 0.0f;
    float h    = hard[node];
    g_x[idx] = prog * g_wc[j] + h * g_wc[HID + j] + atl * g_wc[2 * HID + j] + g_bc[j];
}

// ---------------- K2: xl = x@wl, xr = x@wr (tiled 64x64, 4x4 micro) ----------------
__global__ __launch_bounds__(256) void gemm_lr_kernel(const float* __restrict__ wl,
                                                      const float* __restrict__ wr, int n) {
    __shared__ float xsT[64 * 68];   // [k][node], padded
    __shared__ float ws [64 * 68];   // [k][col],  padded
    int tid   = threadIdx.x;
    int ctile = blockIdx.x;          // 0..7 : 0-3 -> wl, 4-7 -> wr
    int n0    = blockIdx.y * 64;
    const float* w = (ctile < 4) ? wl : wr;
    int cbase = (ctile & 3) * 64;

#pragma unroll
    for (int i = 0; i < 4; i++) {
        int idx = tid + i * 256;             // 0..1023 float4 index
        int r   = idx >> 4;                  // 0..63
        int c4  = (idx & 15) * 4;
        float4 v = make_float4(0.f, 0.f, 0.f, 0.f);
        if (n0 + r < n) v = *(const float4*)&g_x[(n0 + r) * HID + c4];
        xsT[(c4 + 0) * 68 + r] = v.x;
        xsT[(c4 + 1) * 68 + r] = v.y;
        xsT[(c4 + 2) * 68 + r] = v.z;
        xsT[(c4 + 3) * 68 + r] = v.w;
        *(float4*)&ws[r * 68 + c4] = *(const float4*)&w[r * CDIM + cbase + c4];
    }
    __syncthreads();

    int tn = (tid & 15) * 4;
    int tc = (tid >> 4) * 4;
    float acc[4][4];
#pragma unroll
    for (int a = 0; a < 4; a++)
#pragma unroll
        for (int b = 0; b < 4; b++) acc[a][b] = 0.f;

#pragma unroll 16
    for (int k = 0; k < 64; k++) {
        float4 av = *(const float4*)&xsT[k * 68 + tn];
        float4 bv = *(const float4*)&ws [k * 68 + tc];
        float aa[4] = {av.x, av.y, av.z, av.w};
        float bb[4] = {bv.x, bv.y, bv.z, bv.w};
#pragma unroll
        for (int ii = 0; ii < 4; ii++)
#pragma unroll
            for (int jj = 0; jj < 4; jj++) acc[ii][jj] += aa[ii] * bb[jj];
    }

    float* dst = (ctile < 4) ? g_xl : g_xr;
    int cb = cbase + tc;
#pragma unroll
    for (int ii = 0; ii < 4; ii++) {
        int row = n0 + tn + ii;
        if (row < n)
            *(float4*)&dst[row * CDIM + cb] =
                make_float4(acc[ii][0], acc[ii][1], acc[ii][2], acc[ii][3]);
    }
}

// ---------------- CSR build ----------------
__global__ void zero_deg_kernel(int n) {
    int i = blockIdx.x * blockDim.x + threadIdx.x;
    if (i < n) g_deg[i] = 0;
}
__global__ void hist_kernel(const int* __restrict__ ei, int E) {
    int e = blockIdx.x * blockDim.x + threadIdx.x;
    if (e < E) atomicAdd(&g_deg[ei[E + e]], 1);
}
__global__ void scanA_kernel(int n) {
    __shared__ int sm[1024];
    int t = threadIdx.x;
    int idx = blockIdx.x * 1024 + t;
    int v = (idx < n) ? g_deg[idx] : 0;
    sm[t] = v;
    __syncthreads();
    for (int ofs = 1; ofs < 1024; ofs <<= 1) {
        int u = (t >= ofs) ? sm[t - ofs] : 0;
        __syncthreads();
        sm[t] += u;
        __syncthreads();
    }
    if (idx < n) g_off[idx] = sm[t] - v;        // block-local exclusive
    if (t == 1023) g_bsum[blockIdx.x] = sm[1023];
}
__global__ void scanB_kernel(int nb) {
    int run = 0;
    for (int b = 0; b < nb; b++) { int v = g_bsum[b]; g_bsum[b] = run; run += v; }
    g_total = run;
}
__global__ void scanC_kernel(int n) {
    int i = blockIdx.x * blockDim.x + threadIdx.x;
    if (i < n) {
        int o = g_off[i] + g_bsum[i >> 10];
        g_off[i] = o;
        g_cur[i] = o;
    }
    if (i == 0) g_off[n] = g_total;
}
__global__ void scatter_kernel(const int* __restrict__ ei, int E) {
    int e = blockIdx.x * blockDim.x + threadIdx.x;
    if (e >= E) return;
    int src = ei[e];
    int dst = ei[E + e];
    int p = atomicAdd(&g_cur[dst], 1);
    g_csr[p] = src;
}

// ---------------- K3: GAT (one warp per node, online softmax) + LN ----------------
__global__ __launch_bounds__(256) void gat_kernel(const float* __restrict__ att,
                                                  const float* __restrict__ gbias, int n) {
    int warp = (blockIdx.x * blockDim.x + threadIdx.x) >> 5;
    int l = threadIdx.x & 31;
    if (warp >= n) return;
    int i = warp;
    int base = l * 8;          // lane's 8 slots in the 256-wide [head][dim] vector
    int dimb = (l & 7) * 8;    // lane's 8 dims in 0..63 (replicated across head groups)

    float att8[8], xr8[8], xs[8], acc[8];
    *(float4*)&att8[0] = *(const float4*)&att[base];
    *(float4*)&att8[4] = *(const float4*)&att[base + 4];
    *(float4*)&xr8[0]  = *(const float4*)&g_xr[i * CDIM + base];
    *(float4*)&xr8[4]  = *(const float4*)&g_xr[i * CDIM + base + 4];

    // self-loop edge (src = dst = i)
    *(float4*)&xs[0] = *(const float4*)&g_xl[i * CDIM + base];
    *(float4*)&xs[4] = *(const float4*)&g_xl[i * CDIM + base + 4];
    float p = 0.f;
#pragma unroll
    for (int t = 0; t < 8; t++) {
        float v = xs[t] + xr8[t];
        v = fmaxf(v, 0.2f * v);          // leaky relu
        p += v * att8[t];
    }
    p += __shfl_xor_sync(0xffffffffu, p, 1);
    p += __shfl_xor_sync(0xffffffffu, p, 2);
    p += __shfl_xor_sync(0xffffffffu, p, 4);   // per-head score in all 8 lanes of group

    float m = p, s = 1.0f;
#pragma unroll
    for (int t = 0; t < 8; t++) acc[t] = xs[t];

    int e0 = g_off[i], e1 = g_off[i + 1];
    for (int j = e0; j < e1; j++) {
        int src = g_csr[j];
        *(float4*)&xs[0] = *(const float4*)&g_xl[src * CDIM + base];
        *(float4*)&xs[4] = *(const float4*)&g_xl[src * CDIM + base + 4];
        float q = 0.f;
#pragma unroll
        for (int t = 0; t < 8; t++) {
            float v = xs[t] + xr8[t];
            v = fmaxf(v, 0.2f * v);
            q += v * att8[t];
        }
        q += __shfl_xor_sync(0xffffffffu, q, 1);
        q += __shfl_xor_sync(0xffffffffu, q, 2);
        q += __shfl_xor_sync(0xffffffffu, q, 4);
        float mn = fmaxf(m, q);
        float c  = __expf(m - mn);
        float wv = __expf(q - mn);
        s = s * c + wv;
#pragma unroll
        for (int t = 0; t < 8; t++) acc[t] = acc[t] * c + wv * xs[t];
        m = mn;
    }

    float inv = 1.0f / s;
#pragma unroll
    for (int t = 0; t < 8; t++) acc[t] *= inv;

    // sum across the 4 heads (lanes l, l^8, l^16, l^24 hold the same dims)
#pragma unroll
    for (int t = 0; t < 8; t++) {
        float v = acc[t];
        v += __shfl_xor_sync(0xffffffffu, v, 8);
        v += __shfl_xor_sync(0xffffffffu, v, 16);
        acc[t] = v;
    }

    float x8[8], b8[8];
    *(float4*)&x8[0] = *(const float4*)&g_x[i * HID + dimb];
    *(float4*)&x8[4] = *(const float4*)&g_x[i * HID + dimb + 4];
    *(float4*)&b8[0] = *(const float4*)&gbias[dimb];
    *(float4*)&b8[4] = *(const float4*)&gbias[dimb + 4];

    float xv[8];
    float sm = 0.f;
#pragma unroll
    for (int t = 0; t < 8; t++) {
        xv[t] = x8[t] + 0.25f * acc[t] + b8[t];
        sm += xv[t];
    }
    sm += __shfl_xor_sync(0xffffffffu, sm, 1);
    sm += __shfl_xor_sync(0xffffffffu, sm, 2);
    sm += __shfl_xor_sync(0xffffffffu, sm, 4);
    float mu = sm * (1.0f / 64.0f);
    float sq = 0.f;
#pragma unroll
    for (int t = 0; t < 8; t++) { float d = xv[t] - mu; sq += d * d; }
    sq += __shfl_xor_sync(0xffffffffu, sq, 1);
    sq += __shfl_xor_sync(0xffffffffu, sq, 2);
    sq += __shfl_xor_sync(0xffffffffu, sq, 4);
    float rs = rsqrtf(sq * (1.0f / 64.0f) + 1e-5f);

    if (l < 8) {
        float o[8];
#pragma unroll
        for (int t = 0; t < 8; t++) o[t] = (xv[t] - mu) * rs;
        *(float4*)&g_y[i * HID + dimb]     = make_float4(o[0], o[1], o[2], o[3]);
        *(float4*)&g_y[i * HID + dimb + 4] = make_float4(o[4], o[5], o[6], o[7]);
    }
}

// ---------------- K4: two residual ReLU FF layers ----------------
__global__ __launch_bounds__(256) void ff_kernel(const float* __restrict__ w1,
                                                 const float* __restrict__ b1,
                                                 const float* __restrict__ w2,
                                                 const float* __restrict__ b2,
                                                 float* __restrict__ out, int n) {
    __shared__ float ysT[64 * 68];   // [k][node]  (reused for z after stage 1)
    __shared__ float ws [64 * 68];   // [k][col]   (w1 then w2)
    __shared__ float bsh[2 * 64];
    int tid = threadIdx.x;
    int n0  = blockIdx.x * 64;

#pragma unroll
    for (int i = 0; i < 4; i++) {
        int idx = tid + i * 256;
        int r   = idx >> 4;
        int c4  = (idx & 15) * 4;
        float4 v = make_float4(0.f, 0.f, 0.f, 0.f);
        if (n0 + r < n) v = *(const float4*)&g_y[(n0 + r) * HID + c4];
        ysT[(c4 + 0) * 68 + r] = v.x;
        ysT[(c4 + 1) * 68 + r] = v.y;
        ysT[(c4 + 2) * 68 + r] = v.z;
        ysT[(c4 + 3) * 68 + r] = v.w;
        *(float4*)&ws[r * 68 + c4] = *(const float4*)&w1[r * HID + c4];
    }
    if (tid < 64) { bsh[tid] = b1[tid]; bsh[64 + tid] = b2[tid]; }
    __syncthreads();

    int tn = (tid & 15) * 4;
    int tc = (tid >> 4) * 4;

    float z[4][4];
    {
        float acc[4][4];
#pragma unroll
        for (int a = 0; a < 4; a++)
#pragma unroll
            for (int b = 0; b < 4; b++) acc[a][b] = 0.f;
#pragma unroll 16
        for (int k = 0; k < 64; k++) {
            float4 av = *(const float4*)&ysT[k * 68 + tn];
            float4 bv = *(const float4*)&ws [k * 68 + tc];
            float aa[4] = {av.x, av.y, av.z, av.w};
            float bb[4] = {bv.x, bv.y, bv.z, bv.w};
#pragma unroll
            for (int ii = 0; ii < 4; ii++)
#pragma unroll
                for (int jj = 0; jj < 4; jj++) acc[ii][jj] += aa[ii] * bb[jj];
        }
#pragma unroll
        for (int nn = 0; nn < 4; nn++)
#pragma unroll
            for (int cc = 0; cc < 4; cc++) {
                float yv = ysT[(tc + cc) * 68 + tn + nn];
                float r  = acc[nn][cc] + bsh[tc + cc];
                z[nn][cc] = yv + fmaxf(r, 0.f);
            }
    }
    __syncthreads();   // everyone done reading ysT / ws

    // overwrite ysT with z (transposed), reload ws with w2
#pragma unroll
    for (int cc = 0; cc < 4; cc++)
        *(float4*)&ysT[(tc + cc) * 68 + tn] =
            make_float4(z[0][cc], z[1][cc], z[2][cc], z[3][cc]);
#pragma unroll
    for (int i = 0; i < 4; i++) {
        int idx = tid + i * 256;
        int r   = idx >> 4;
        int c4  = (idx & 15) * 4;
        *(float4*)&ws[r * 68 + c4] = *(const float4*)&w2[r * HID + c4];
    }
    __syncthreads();

    float acc2[4][4];
#pragma unroll
    for (int a = 0; a < 4; a++)
#pragma unroll
        for (int b = 0; b < 4; b++) acc2[a][b] = 0.f;
#pragma unroll 16
    for (int k = 0; k < 64; k++) {
        float4 av = *(const float4*)&ysT[k * 68 + tn];
        float4 bv = *(const float4*)&ws [k * 68 + tc];
        float aa[4] = {av.x, av.y, av.z, av.w};
        float bb[4] = {bv.x, bv.y, bv.z, bv.w};
#pragma unroll
        for (int ii = 0; ii < 4; ii++)
#pragma unroll
            for (int jj = 0; jj < 4; jj++) acc2[ii][jj] += aa[ii] * bb[jj];
    }
#pragma unroll
    for (int nn = 0; nn < 4; nn++) {
        int row = n0 + tn + nn;
        if (row < n) {
            float o[4];
#pragma unroll
            for (int cc = 0; cc < 4; cc++) {
                float zv = ysT[(tc + cc) * 68 + tn + nn];
                float r2 = acc2[nn][cc] + bsh[64 + tc + cc];
                o[cc] = zv + fmaxf(r2, 0.f);
            }
            *(float4*)&out[row * HID + tc] = make_float4(o[0], o[1], o[2], o[3]);
        }
    }
}

// ---------------- launch ----------------
extern "C" void kernel_launch(void* const* d_in, const int* in_sizes, int n_in,
                              void* d_out, int out_size) {
    const float* arrivals = (const float*)d_in[0];
    const float* departs  = (const float*)d_in[1];
    const float* hard     = (const float*)d_in[2];
    const float* w_emb1   = (const float*)d_in[3];
    const float* b_emb1   = (const float*)d_in[4];
    const float* w_emb2   = (const float*)d_in[5];
    const float* b_emb2   = (const float*)d_in[6];
    const float* gat_wl   = (const float*)d_in[7];
    const float* gat_wr   = (const float*)d_in[8];
    const float* gat_att  = (const float*)d_in[9];
    const float* gat_bias = (const float*)d_in[10];
    const float* w_ff1    = (const float*)d_in[11];
    const float* b_ff1    = (const float*)d_in[12];
    const float* w_ff2    = (const float*)d_in[13];
    const float* b_ff2    = (const float*)d_in[14];
    const int*   edge     = (const int*)d_in[15];
    const void*  tptr     = d_in[16];

    int n = in_sizes[0];
    int E = in_sizes[15] / 2;

    prep_kernel<<<1, 64>>>(w_emb1, b_emb1, w_emb2, b_emb2);
    feat_kernel<<<(n * HID + 255) / 256, 256>>>(arrivals, departs, hard, tptr, n);

    dim3 gg(8, (n + 63) / 64);
    gemm_lr_kernel<<<gg, 256>>>(gat_wl, gat_wr, n);

    zero_deg_kernel<<<(n + 255) / 256, 256>>>(n);
    hist_kernel<<<(E + 255) / 256, 256>>>(edge, E);
    int nb = (n + 1023) / 1024;
    scanA_kernel<<<nb, 1024>>>(n);
    scanB_kernel<<<1, 1>>>(nb);
    scanC_kernel<<<(n + 255) / 256, 256>>>(n);
    scatter_kernel<<<(E + 255) / 256, 256>>>(edge, E);

    gat_kernel<<<(n + 7) / 8, 256>>>(gat_att, gat_bias, n);

    ff_kernel<<<(n + 63) / 64, 256>>>(w_ff1, b_ff1, w_ff2, b_ff2, (float*)d_out, n);
}

// round 2
// speedup vs baseline: 1.3515x; 1.3515x over previous
#include <cuda_runtime.h>

#define HID   64
#define CDIM  256     // HEADS*HID
#define NMAX  65536
#define EMAX  524288

// ---------------- scratch (static device arrays; no allocation) ----------------
__device__ float g_wc [3 * HID];         // combined embedding weight [3][64]
__device__ float g_bc [HID];             // combined embedding bias
__device__ float g_WL3[3 * CDIM];        // Wc @ gat_wl  [3][256]
__device__ float g_bL [CDIM];            // bc @ gat_wl + 0
__device__ float g_WR3[3 * CDIM];        // Wc @ gat_wr  [3][256]
__device__ float g_bR [CDIM];
__device__ float g_xl[NMAX * CDIM];      // x @ gat_wl  (gather operand)
__device__ float g_y [NMAX * HID];       // post-LN features
__device__ int   g_deg [NMAX];
__device__ int   g_off [NMAX + 1];
__device__ int   g_cur [NMAX];
__device__ int   g_bsum[64];
__device__ int   g_total;
__device__ int   g_csr [EMAX];           // src per dst-sorted edge

// ---------------- helpers ----------------
__device__ __forceinline__ float decode_t(const void* p) {
    int iv = *(const int*)p;
    if (iv > -16777216 && iv < 16777216) return (float)iv;   // int32 / int64 low word
    return __int_as_float(iv);                               // float32
}

// ---------------- K0: combine all static weights ----------------
__global__ void prep_kernel(const float* __restrict__ w1, const float* __restrict__ b1,
                            const float* __restrict__ w2, const float* __restrict__ b2,
                            const float* __restrict__ wl, const float* __restrict__ wr) {
    __shared__ float sWc[3 * HID];
    __shared__ float sbc[HID];
    int t = threadIdx.x;   // 256 threads
    if (t < HID) {
        float c0 = 0.f, c1 = 0.f, c2 = 0.f, cb = 0.f;
        for (int k = 0; k < HID; k++) {
            float wkj = w2[k * HID + t];
            c0 += w1[k] * wkj;
            c1 += w1[HID + k] * wkj;
            c2 += w1[2 * HID + k] * wkj;
            cb += b1[k] * wkj;
        }
        float bcv = cb + b2[t];
        sWc[t] = c0; sWc[HID + t] = c1; sWc[2 * HID + t] = c2; sbc[t] = bcv;
        g_wc[t] = c0; g_wc[HID + t] = c1; g_wc[2 * HID + t] = c2; g_bc[t] = bcv;
    }
    __syncthreads();
    int c = t;             // 0..255
    float l0 = 0.f, l1 = 0.f, l2 = 0.f, lb = 0.f;
    float r0 = 0.f, r1 = 0.f, r2 = 0.f, rb = 0.f;
    for (int j = 0; j < HID; j++) {
        float wlv = wl[j * CDIM + c], wrv = wr[j * CDIM + c];
        float wc0 = sWc[j], wc1 = sWc[HID + j], wc2 = sWc[2 * HID + j], bcv = sbc[j];
        l0 += wc0 * wlv; l1 += wc1 * wlv; l2 += wc2 * wlv; lb += bcv * wlv;
        r0 += wc0 * wrv; r1 += wc1 * wrv; r2 += wc2 * wrv; rb += bcv * wrv;
    }
    g_WL3[c] = l0; g_WL3[CDIM + c] = l1; g_WL3[2 * CDIM + c] = l2; g_bL[c] = lb;
    g_WR3[c] = r0; g_WR3[CDIM + c] = r1; g_WR3[2 * CDIM + c] = r2; g_bR[c] = rb;
}

// ---------------- K1: xl = in_data @ WL3 + bL  (3 FMAs/elem, write-bound) ----------------
__global__ __launch_bounds__(256) void xl_kernel(const float* __restrict__ arr,
                                                 const float* __restrict__ dep,
                                                 const float* __restrict__ hard,
                                                 const void* __restrict__ tptr, int n) {
    int idx = blockIdx.x * blockDim.x + threadIdx.x;
    int node = idx >> 5;
    if (node >= n) return;
    int c = (idx & 31) * 8;
    float t = decode_t(tptr);
    float a = arr[node], d = dep[node], h = hard[node];
    float prog = (t - a) / fmaxf(d - a, 1.0f);
    float atl  = ((d - t) <= 1.0f) ? 1.0f : 0.0f;

    float4 wa0 = *(const float4*)&g_WL3[c];
    float4 wa1 = *(const float4*)&g_WL3[c + 4];
    float4 wb0 = *(const float4*)&g_WL3[CDIM + c];
    float4 wb1 = *(const float4*)&g_WL3[CDIM + c + 4];
    float4 wc0 = *(const float4*)&g_WL3[2 * CDIM + c];
    float4 wc1 = *(const float4*)&g_WL3[2 * CDIM + c + 4];
    float4 bb0 = *(const float4*)&g_bL[c];
    float4 bb1 = *(const float4*)&g_bL[c + 4];

    float4 o0, o1;
    o0.x = prog * wa0.x + h * wb0.x + atl * wc0.x + bb0.x;
    o0.y = prog * wa0.y + h * wb0.y + atl * wc0.y + bb0.y;
    o0.z = prog * wa0.z + h * wb0.z + atl * wc0.z + bb0.z;
    o0.w = prog * wa0.w + h * wb0.w + atl * wc0.w + bb0.w;
    o1.x = prog * wa1.x + h * wb1.x + atl * wc1.x + bb1.x;
    o1.y = prog * wa1.y + h * wb1.y + atl * wc1.y + bb1.y;
    o1.z = prog * wa1.z + h * wb1.z + atl * wc1.z + bb1.z;
    o1.w = prog * wa1.w + h * wb1.w + atl * wc1.w + bb1.w;
    *(float4*)&g_xl[node * CDIM + c]     = o0;
    *(float4*)&g_xl[node * CDIM + c + 4] = o1;
    if ((idx & 31) == 0) g_deg[node] = 0;
}

// ---------------- CSR build ----------------
__global__ void hist_kernel(const int* __restrict__ ei, int E) {
    int e = blockIdx.x * blockDim.x + threadIdx.x;
    if (e < E) atomicAdd(&g_deg[ei[E + e]], 1);
}
__global__ void scanA_kernel(int n) {
    __shared__ int sm[1024];
    int t = threadIdx.x;
    int idx = blockIdx.x * 1024 + t;
    int v = (idx < n) ? g_deg[idx] : 0;
    sm[t] = v;
    __syncthreads();
    for (int ofs = 1; ofs < 1024; ofs <<= 1) {
        int u = (t >= ofs) ? sm[t - ofs] : 0;
        __syncthreads();
        sm[t] += u;
        __syncthreads();
    }
    if (idx < n) g_off[idx] = sm[t] - v;        // block-local exclusive
    if (t == 1023) g_bsum[blockIdx.x] = sm[1023];
}
__global__ void scanB_kernel(int nb) {         // single-warp scan over <=64 block sums
    int l = threadIdx.x;
    int i0 = 2 * l, i1 = 2 * l + 1;
    int v0 = (i0 < nb) ? g_bsum[i0] : 0;
    int v1 = (i1 < nb) ? g_bsum[i1] : 0;
    int pair = v0 + v1;
    int run = pair;
#pragma unroll
    for (int ofs = 1; ofs < 32; ofs <<= 1) {
        int u = __shfl_up_sync(0xffffffffu, run, ofs);
        if (l >= ofs) run += u;
    }
    int excl = run - pair;
    if (i0 < nb) g_bsum[i0] = excl;
    if (i1 < nb) g_bsum[i1] = excl + v0;
    if (l == 31) g_total = run;
}
__global__ void scanC_kernel(int n) {
    int i = blockIdx.x * blockDim.x + threadIdx.x;
    if (i < n) {
        int o = g_off[i] + g_bsum[i >> 10];
        g_off[i] = o;
        g_cur[i] = o;
    }
    if (i == 0) g_off[n] = g_total;
}
__global__ void scatter_kernel(const int* __restrict__ ei, int E) {
    int e = blockIdx.x * blockDim.x + threadIdx.x;
    if (e >= E) return;
    int src = ei[e];
    int dst = ei[E + e];
    int p = atomicAdd(&g_cur[dst], 1);
    g_csr[p] = src;
}

// ---------------- K3: GAT (warp/node, online softmax, x2 unroll) + LN ----------------
__global__ __launch_bounds__(256) void gat_kernel(const float* __restrict__ att,
                                                  const float* __restrict__ gbias,
                                                  const float* __restrict__ arr,
                                                  const float* __restrict__ dep,
                                                  const float* __restrict__ hard,
                                                  const void* __restrict__ tptr, int n) {
    int warp = (blockIdx.x * blockDim.x + threadIdx.x) >> 5;
    if (warp >= n) return;
    int l = threadIdx.x & 31;
    int i = warp;
    int base = l * 8;          // lane's 8 slots in the 256-wide [head][dim] vector
    int dimb = (l & 7) * 8;    // lane's 8 dims in 0..63

    float t = decode_t(tptr);
    float a = arr[i], d = dep[i], h = hard[i];
    float prog = (t - a) / fmaxf(d - a, 1.0f);
    float atl  = ((d - t) <= 1.0f) ? 1.0f : 0.0f;

    float att8[8], xr8[8], xs[8], acc[8];
    *(float4*)&att8[0] = *(const float4*)&att[base];
    *(float4*)&att8[4] = *(const float4*)&att[base + 4];
#pragma unroll
    for (int u = 0; u < 8; u++)
        xr8[u] = prog * g_WR3[base + u] + h * g_WR3[CDIM + base + u]
               + atl * g_WR3[2 * CDIM + base + u] + g_bR[base + u];

    // self-loop edge (src = dst = i)
    *(float4*)&xs[0] = *(const float4*)&g_xl[i * CDIM + base];
    *(float4*)&xs[4] = *(const float4*)&g_xl[i * CDIM + base + 4];
    float p = 0.f;
#pragma unroll
    for (int u = 0; u < 8; u++) {
        float v = xs[u] + xr8[u];
        v = fmaxf(v, 0.2f * v);
        p += v * att8[u];
    }
    p += __shfl_xor_sync(0xffffffffu, p, 1);
    p += __shfl_xor_sync(0xffffffffu, p, 2);
    p += __shfl_xor_sync(0xffffffffu, p, 4);

    float m = p, s = 1.0f;
#pragma unroll
    for (int u = 0; u < 8; u++) acc[u] = xs[u];

    int e0 = g_off[i], e1 = g_off[i + 1];
    int j = e0;
    for (; j + 1 < e1; j += 2) {
        int s0 = g_csr[j], s1 = g_csr[j + 1];
        float y0[8], y1[8];
        *(float4*)&y0[0] = *(const float4*)&g_xl[s0 * CDIM + base];
        *(float4*)&y0[4] = *(const float4*)&g_xl[s0 * CDIM + base + 4];
        *(float4*)&y1[0] = *(const float4*)&g_xl[s1 * CDIM + base];
        *(float4*)&y1[4] = *(const float4*)&g_xl[s1 * CDIM + base + 4];
        float q0 = 0.f, q1 = 0.f;
#pragma unroll
        for (int u = 0; u < 8; u++) {
            float v0 = y0[u] + xr8[u];
            float v1 = y1[u] + xr8[u];
            v0 = fmaxf(v0, 0.2f * v0);
            v1 = fmaxf(v1, 0.2f * v1);
            q0 += v0 * att8[u];
            q1 += v1 * att8[u];
        }
        q0 += __shfl_xor_sync(0xffffffffu, q0, 1);
        q1 += __shfl_xor_sync(0xffffffffu, q1, 1);
        q0 += __shfl_xor_sync(0xffffffffu, q0, 2);
        q1 += __shfl_xor_sync(0xffffffffu, q1, 2);
        q0 += __shfl_xor_sync(0xffffffffu, q0, 4);
        q1 += __shfl_xor_sync(0xffffffffu, q1, 4);
        float mn = fmaxf(m, fmaxf(q0, q1));
        float c  = __expf(m - mn);
        float w0 = __expf(q0 - mn);
        float w1 = __expf(q1 - mn);
        s = s * c + w0 + w1;
#pragma unroll
        for (int u = 0; u < 8; u++) acc[u] = acc[u] * c + w0 * y0[u] + w1 * y1[u];
        m = mn;
    }
    if (j < e1) {
        int src = g_csr[j];
        *(float4*)&xs[0] = *(const float4*)&g_xl[src * CDIM + base];
        *(float4*)&xs[4] = *(const float4*)&g_xl[src * CDIM + base + 4];
        float q = 0.f;
#pragma unroll
        for (int u = 0; u < 8; u++) {
            float v = xs[u] + xr8[u];
            v = fmaxf(v, 0.2f * v);
            q += v * att8[u];
        }
        q += __shfl_xor_sync(0xffffffffu, q, 1);
        q += __shfl_xor_sync(0xffffffffu, q, 2);
        q += __shfl_xor_sync(0xffffffffu, q, 4);
        float mn = fmaxf(m, q);
        float c  = __expf(m - mn);
        float wv = __expf(q - mn);
        s = s * c + wv;
#pragma unroll
        for (int u = 0; u < 8; u++) acc[u] = acc[u] * c + wv * xs[u];
        m = mn;
    }

    float inv = 1.0f / s;
#pragma unroll
    for (int u = 0; u < 8; u++) acc[u] *= inv;

    // sum across the 4 heads (lanes l, l^8, l^16, l^24 hold the same dims)
#pragma unroll
    for (int u = 0; u < 8; u++) {
        float v = acc[u];
        v += __shfl_xor_sync(0xffffffffu, v, 8);
        v += __shfl_xor_sync(0xffffffffu, v, 16);
        acc[u] = v;
    }

    // residual x recomputed from features + LN
    float x8[8], b8[8];
#pragma unroll
    for (int u = 0; u < 8; u++)
        x8[u] = prog * g_wc[dimb + u] + h * g_wc[HID + dimb + u]
              + atl * g_wc[2 * HID + dimb + u] + g_bc[dimb + u];
    *(float4*)&b8[0] = *(const float4*)&gbias[dimb];
    *(float4*)&b8[4] = *(const float4*)&gbias[dimb + 4];

    float xv[8];
    float sm = 0.f;
#pragma unroll
    for (int u = 0; u < 8; u++) {
        xv[u] = x8[u] + 0.25f * acc[u] + b8[u];
        sm += xv[u];
    }
    sm += __shfl_xor_sync(0xffffffffu, sm, 1);
    sm += __shfl_xor_sync(0xffffffffu, sm, 2);
    sm += __shfl_xor_sync(0xffffffffu, sm, 4);
    float mu = sm * (1.0f / 64.0f);
    float sq = 0.f;
#pragma unroll
    for (int u = 0; u < 8; u++) { float dd = xv[u] - mu; sq += dd * dd; }
    sq += __shfl_xor_sync(0xffffffffu, sq, 1);
    sq += __shfl_xor_sync(0xffffffffu, sq, 2);
    sq += __shfl_xor_sync(0xffffffffu, sq, 4);
    float rs = rsqrtf(sq * (1.0f / 64.0f) + 1e-5f);

    if (l < 8) {
        float o[8];
#pragma unroll
        for (int u = 0; u < 8; u++) o[u] = (xv[u] - mu) * rs;
        *(float4*)&g_y[i * HID + dimb]     = make_float4(o[0], o[1], o[2], o[3]);
        *(float4*)&g_y[i * HID + dimb + 4] = make_float4(o[4], o[5], o[6], o[7]);
    }
}

// ---------------- K4: two residual ReLU FF layers ----------------
__global__ __launch_bounds__(256) void ff_kernel(const float* __restrict__ w1,
                                                 const float* __restrict__ b1,
                                                 const float* __restrict__ w2,
                                                 const float* __restrict__ b2,
                                                 float* __restrict__ out, int n) {
    __shared__ float ysT[64 * 68];
    __shared__ float ws [64 * 68];
    __shared__ float bsh[2 * 64];
    int tid = threadIdx.x;
    int n0  = blockIdx.x * 64;

#pragma unroll
    for (int i = 0; i < 4; i++) {
        int idx = tid + i * 256;
        int r   = idx >> 4;
        int c4  = (idx & 15) * 4;
        float4 v = make_float4(0.f, 0.f, 0.f, 0.f);
        if (n0 + r < n) v = *(const float4*)&g_y[(n0 + r) * HID + c4];
        ysT[(c4 + 0) * 68 + r] = v.x;
        ysT[(c4 + 1) * 68 + r] = v.y;
        ysT[(c4 + 2) * 68 + r] = v.z;
        ysT[(c4 + 3) * 68 + r] = v.w;
        *(float4*)&ws[r * 68 + c4] = *(const float4*)&w1[r * HID + c4];
    }
    if (tid < 64) { bsh[tid] = b1[tid]; bsh[64 + tid] = b2[tid]; }
    __syncthreads();

    int tn = (tid & 15) * 4;
    int tc = (tid >> 4) * 4;

    float z[4][4];
    {
        float acc[4][4];
#pragma unroll
        for (int aa = 0; aa < 4; aa++)
#pragma unroll
            for (int bb = 0; bb < 4; bb++) acc[aa][bb] = 0.f;
#pragma unroll 16
        for (int k = 0; k < 64; k++) {
            float4 av = *(const float4*)&ysT[k * 68 + tn];
            float4 bv = *(const float4*)&ws [k * 68 + tc];
            float a4[4] = {av.x, av.y, av.z, av.w};
            float b4[4] = {bv.x, bv.y, bv.z, bv.w};
#pragma unroll
            for (int ii = 0; ii < 4; ii++)
#pragma unroll
                for (int jj = 0; jj < 4; jj++) acc[ii][jj] += a4[ii] * b4[jj];
        }
#pragma unroll
        for (int nn = 0; nn < 4; nn++)
#pragma unroll
            for (int cc = 0; cc < 4; cc++) {
                float yv = ysT[(tc + cc) * 68 + tn + nn];
                float r  = acc[nn][cc] + bsh[tc + cc];
                z[nn][cc] = yv + fmaxf(r, 0.f);
            }
    }
    __syncthreads();

#pragma unroll
    for (int cc = 0; cc < 4; cc++)
        *(float4*)&ysT[(tc + cc) * 68 + tn] =
            make_float4(z[0][cc], z[1][cc], z[2][cc], z[3][cc]);
#pragma unroll
    for (int i = 0; i < 4; i++) {
        int idx = tid + i * 256;
        int r   = idx >> 4;
        int c4  = (idx & 15) * 4;
        *(float4*)&ws[r * 68 + c4] = *(const float4*)&w2[r * HID + c4];
    }
    __syncthreads();

    float acc2[4][4];
#pragma unroll
    for (int aa = 0; aa < 4; aa++)
#pragma unroll
        for (int bb = 0; bb < 4; bb++) acc2[aa][bb] = 0.f;
#pragma unroll 16
    for (int k = 0; k < 64; k++) {
        float4 av = *(const float4*)&ysT[k * 68 + tn];
        float4 bv = *(const float4*)&ws [k * 68 + tc];
        float a4[4] = {av.x, av.y, av.z, av.w};
        float b4[4] = {bv.x, bv.y, bv.z, bv.w};
#pragma unroll
        for (int ii = 0; ii < 4; ii++)
#pragma unroll
            for (int jj = 0; jj < 4; jj++) acc2[ii][jj] += a4[ii] * b4[jj];
    }
#pragma unroll
    for (int nn = 0; nn < 4; nn++) {
        int row = n0 + tn + nn;
        if (row < n) {
            float o[4];
#pragma unroll
            for (int cc = 0; cc < 4; cc++) {
                float zv = ysT[(tc + cc) * 68 + tn + nn];
                float r2 = acc2[nn][cc] + bsh[64 + tc + cc];
                o[cc] = zv + fmaxf(r2, 0.f);
            }
            *(float4*)&out[row * HID + tc] = make_float4(o[0], o[1], o[2], o[3]);
        }
    }
}

// ---------------- launch ----------------
extern "C" void kernel_launch(void* const* d_in, const int* in_sizes, int n_in,
                              void* d_out, int out_size) {
    const float* arrivals = (const float*)d_in[0];
    const float* departs  = (const float*)d_in[1];
    const float* hard     = (const float*)d_in[2];
    const float* w_emb1   = (const float*)d_in[3];
    const float* b_emb1   = (const float*)d_in[4];
    const float* w_emb2   = (const float*)d_in[5];
    const float* b_emb2   = (const float*)d_in[6];
    const float* gat_wl   = (const float*)d_in[7];
    const float* gat_wr   = (const float*)d_in[8];
    const float* gat_att  = (const float*)d_in[9];
    const float* gat_bias = (const float*)d_in[10];
    const float* w_ff1    = (const float*)d_in[11];
    const float* b_ff1    = (const float*)d_in[12];
    const float* w_ff2    = (const float*)d_in[13];
    const float* b_ff2    = (const float*)d_in[14];
    const int*   edge     = (const int*)d_in[15];
    const void*  tptr     = d_in[16];

    int n = in_sizes[0];
    int E = in_sizes[15] / 2;

    prep_kernel<<<1, 256>>>(w_emb1, b_emb1, w_emb2, b_emb2, gat_wl, gat_wr);
    xl_kernel<<<(n * 32 + 255) / 256, 256>>>(arrivals, departs, hard, tptr, n);

    hist_kernel<<<(E + 255) / 256, 256>>>(edge, E);
    int nb = (n + 1023) / 1024;
    scanA_kernel<<<nb, 1024>>>(n);
    scanB_kernel<<<1, 32>>>(nb);
    scanC_kernel<<<(n + 255) / 256, 256>>>(n);
    scatter_kernel<<<(E + 255) / 256, 256>>>(edge, E);

    gat_kernel<<<(n + 7) / 8, 256>>>(gat_att, gat_bias, arrivals, departs, hard, tptr, n);

    ff_kernel<<<(n + 63) / 64, 256>>>(w_ff1, b_ff1, w_ff2, b_ff2, (float*)d_out, n);
}